// round 4
// baseline (speedup 1.0000x reference)
#include <cuda_runtime.h>
#include <math.h>

// Inputs (metadata order): y[16M] f32, mu[16M] f32, std[16M] f32, idx[200*100] i32
// Output: 1 x f32 (KL scalar)

#define NUM_SAMPLES 200
#define KDOF 100
#define VEC   (KDOF / 4)   // 25 int4 index vectors per sample

// Scratch (no device allocation allowed). g_count returns to 0 each launch.
__device__ float        g_q[NUM_SAMPLES];
__device__ unsigned int g_count = 0;

// 200 blocks x 32 threads (one warp per sample). No __syncthreads anywhere.
__global__ void __launch_bounds__(32) fused_chi2_kl_kernel(
    const float* __restrict__ y,
    const float* __restrict__ mu,
    const float* __restrict__ sd,
    const int*   __restrict__ idx,
    float*       __restrict__ out)
{
    const int s = blockIdx.x;
    const int t = threadIdx.x;

    // ---- Phase 1: per-sample chi-square statistic (one warp) ----
    float v = 0.0f;
    if (t < VEC) {
        // one vectorized index load -> 4 indices
        const int4 i4 = reinterpret_cast<const int4*>(idx)[s * VEC + t];

        // 12 independent gathers, latency fully overlapped
        const float y0 = __ldg(y + i4.x), y1 = __ldg(y + i4.y);
        const float y2 = __ldg(y + i4.z), y3 = __ldg(y + i4.w);
        const float m0 = __ldg(mu + i4.x), m1 = __ldg(mu + i4.y);
        const float m2 = __ldg(mu + i4.z), m3 = __ldg(mu + i4.w);
        const float s0 = __ldg(sd + i4.x), s1 = __ldg(sd + i4.y);
        const float s2 = __ldg(sd + i4.z), s3 = __ldg(sd + i4.w);

        const float d0 = __fdividef(y0 - m0, s0);
        const float d1 = __fdividef(y1 - m1, s1);
        const float d2 = __fdividef(y2 - m2, s2);
        const float d3 = __fdividef(y3 - m3, s3);
        v = d0 * d0 + d1 * d1 + d2 * d2 + d3 * d3;
    }

    // Butterfly reduce (all lanes end with q)
    #pragma unroll
    for (int o = 16; o > 0; o >>= 1)
        v += __shfl_xor_sync(0xFFFFFFFFu, v, o);

    // Lane 0 publishes q and takes a ticket; flag broadcast to the warp.
    unsigned int last = 0;
    if (t == 0) {
        g_q[s] = v;
        __threadfence();                       // release g_q[s] before ticket
        last = (atomicAdd(&g_count, 1u) == NUM_SAMPLES - 1u) ? 1u : 0u;
    }
    last = __shfl_sync(0xFFFFFFFFu, last, 0);
    if (!last) return;

    // ---- Phase 2 (last warp): centered mean/var over 200 q's, then KL ----
    __threadfence();                           // acquire: see all g_q stores

    float q[7];
    float sum = 0.0f;
    #pragma unroll
    for (int j = 0; j < 7; j++) {
        const int i = t + 32 * j;
        q[j] = (i < NUM_SAMPLES) ? g_q[i] : 0.0f;
        sum += q[j];
    }
    #pragma unroll
    for (int o = 16; o > 0; o >>= 1)
        sum += __shfl_xor_sync(0xFFFFFFFFu, sum, o);

    const float mean = sum * (1.0f / (float)NUM_SAMPLES);

    float ss = 0.0f;
    #pragma unroll
    for (int j = 0; j < 7; j++) {
        const int i = t + 32 * j;
        if (i < NUM_SAMPLES) {
            const float d = q[j] - mean;
            ss += d * d;
        }
    }
    #pragma unroll
    for (int o = 16; o > 0; o >>= 1)
        ss += __shfl_xor_sync(0xFFFFFFFFu, ss, o);

    if (t == 0) {
        const float var   = ss / (float)(NUM_SAMPLES - 1);
        const float k     = (float)KDOF;
        const float two_k = 2.0f * k;
        const float dm    = mean - k;
        out[0] = 0.5f * logf(two_k / var)
               + (var + dm * dm) / (2.0f * two_k)
               - 0.5f;
        g_count = 0;                           // reset for next graph replay
    }
}

extern "C" void kernel_launch(void* const* d_in, const int* in_sizes, int n_in,
                              void* d_out, int out_size)
{
    const float* y   = (const float*)d_in[0];
    const float* mu  = (const float*)d_in[1];
    const float* sd  = (const float*)d_in[2];
    const int*   idx = (const int*)d_in[3];
    float* out = (float*)d_out;

    fused_chi2_kl_kernel<<<NUM_SAMPLES, 32>>>(y, mu, sd, idx, out);
}

// round 5
// speedup vs baseline: 1.2694x; 1.2694x over previous
#include <cuda_runtime.h>
#include <math.h>

// Inputs (metadata order): y[16M] f32, mu[16M] f32, std[16M] f32, idx[200*100] i32
// Output: 1 x f32 (KL scalar)

#define NUM_SAMPLES 200
#define KDOF 100

// Scratch (no device allocation allowed). Reset by the winner each launch so
// graph replays are self-consistent.
__device__ float        g_s1 = 0.0f;   // sum of (q - K)
__device__ float        g_s2 = 0.0f;   // sum of (q - K)^2
__device__ unsigned int g_count = 0;

// 200 blocks x 128 threads. Block s computes q_s, folds shifted moments into
// fp32 global atomics; the last-finishing block computes the KL scalar.
__global__ void __launch_bounds__(128) fused_chi2_kl_kernel(
    const float* __restrict__ y,
    const float* __restrict__ mu,
    const float* __restrict__ sd,
    const int*   __restrict__ idx,
    float*       __restrict__ out)
{
    const int s = blockIdx.x;
    const int t = threadIdx.x;

    // ---- Phase 1: per-sample chi-square statistic ----
    float v = 0.0f;
    if (t < KDOF) {
        const int i = idx[s * KDOF + t];
        // three independent gathers -> MLP=3 per thread, 4 warps share the load queue
        const float d = __fdividef(y[i] - mu[i], sd[i]);
        v = d * d;
    }

    #pragma unroll
    for (int o = 16; o > 0; o >>= 1)
        v += __shfl_down_sync(0xFFFFFFFFu, v, o);

    __shared__ float sm[4];
    if ((t & 31) == 0) sm[t >> 5] = v;
    __syncthreads();

    if (t != 0) return;

    // Shifted statistic: p = q - K  (kills cancellation in the var formula)
    const float p = (sm[0] + sm[1] + sm[2] + sm[3]) - (float)KDOF;

    atomicAdd(&g_s1, p);
    atomicAdd(&g_s2, p * p);
    __threadfence();                            // publish sums before ticket

    if (atomicAdd(&g_count, 1u) != NUM_SAMPLES - 1u) return;

    // ---- Phase 2 (single thread, last block): KL from shifted moments ----
    __threadfence();                            // acquire: see all atomic sums

    const float s1 = g_s1;
    const float s2 = g_s2;

    const float inv_n  = 1.0f / (float)NUM_SAMPLES;
    const float dm     = s1 * inv_n;                         // emp_mu - K
    const float var    = (s2 - s1 * s1 * inv_n)
                         * (1.0f / (float)(NUM_SAMPLES - 1)); // unbiased var
    const float two_k  = 2.0f * (float)KDOF;

    out[0] = 0.5f * __logf(two_k / var)
           + (var + dm * dm) / (2.0f * two_k)
           - 0.5f;

    // Reset scratch for next replay.
    g_s1 = 0.0f;
    g_s2 = 0.0f;
    g_count = 0;
}

extern "C" void kernel_launch(void* const* d_in, const int* in_sizes, int n_in,
                              void* d_out, int out_size)
{
    const float* y   = (const float*)d_in[0];
    const float* mu  = (const float*)d_in[1];
    const float* sd  = (const float*)d_in[2];
    const int*   idx = (const int*)d_in[3];
    float* out = (float*)d_out;

    fused_chi2_kl_kernel<<<NUM_SAMPLES, 128>>>(y, mu, sd, idx, out);
}